// round 13
// baseline (speedup 1.0000x reference)
#include <cuda_runtime.h>
#include <cuda.h>
#include <cuda_fp16.h>
#include <cstdint>

// ============================================================================
// convDU: bidirectional recurrent conv along H.
//   step: y = relu(Wm @ carry + b) + x     (Wm = W[:,:,4,0], 2048x2048)
// 94 serial GEMM steps of [2048x2048]x[2048x384].
// Base-ISA tensor cores: TMA+mbarrier pipeline -> ldmatrix -> mma.sync
// m16n8k16 f16, fp32 accum. Mainloop is at the sm_103a legacy-mma SM
// throughput wall (~227cyc/48 HMMA/SM, schedule-invariant: R5/R9/R11).
// R13: persistent DATAFLOW kernel. No global step barrier, no per-step
// launches. K-chunk `it` of step s+1 depends on exactly one producer CTA
// (m-tile it, same n-tile) -> per-(nt,mt) progress flags, polled by the TMA
// warp. Carry ping-pong buffered (2 tensor maps). Mainloop/epilogue are
// byte-identical to validated R5 (best: 1230.8us).
// ============================================================================

#define CDU_C   2048
#define CDU_NB  4
#define CDU_H   48
#define CDU_W   96
#define CDU_NW  (CDU_NB * CDU_W)     // 384
#define CDU_HW  (CDU_H * CDU_W)      // 4608
#define NSTEPS  (2 * CDU_H - 2)      // 94

#define M_TILE  64
#define N_TILE  96                   // one image's w-columns per CTA
#define KC      64                   // k elems per stage; == M_TILE (1:1 chunk->producer)
#define KITERS  (CDU_C / KC)         // 32
#define STAGES  6

#define A_STAGE_BYTES (M_TILE * 128)     // 8192
#define B_STAGE_BYTES (N_TILE * 128)     // 12288
#define SMEM_BAR      64                 // full[s] @ 64+16s, empty[s] @ +8
#define SMEM_A        1024
#define SMEM_B        (SMEM_A + STAGES * A_STAGE_BYTES)     // 50176
#define SMEM_TOTAL    (SMEM_B + STAGES * B_STAGE_BYTES)     // 123904

// fp16 scratch: converted weight matrix + ping-pong recurrent carry
__device__ __align__(16) __half g_Wh[CDU_C * CDU_C];
__device__ __align__(16) __half g_carry[2][CDU_NW * CDU_C];
// per-(ntile, mtile) progress flags: number of completed steps
__device__ int g_flag[CDU_NB][KITERS];

// ---------------------------------------------------------------------------
// PTX helpers (base-ISA only)
// ---------------------------------------------------------------------------
__device__ __forceinline__ uint32_t elect_one_pred() {
    uint32_t pred;
    asm volatile(
        "{\n\t.reg .pred p;\n\telect.sync _|p, 0xFFFFFFFF;\n\t"
        "selp.b32 %0, 1, 0, p;\n\t}" : "=r"(pred));
    return pred;
}
__device__ __forceinline__ uint32_t smem_to_u32(const void* p) {
    uint32_t a;
    asm("{ .reg .u64 t; cvta.to.shared.u64 t, %1; cvt.u32.u64 %0, t; }" : "=r"(a) : "l"(p));
    return a;
}
__device__ __forceinline__ int ld_acquire_gpu(const int* p) {
    int v;
    asm volatile("ld.acquire.gpu.b32 %0, [%1];" : "=r"(v) : "l"(p) : "memory");
    return v;
}

#define MBARRIER_INIT(addr, cnt) \
    asm volatile("mbarrier.init.shared.b64 [%0], %1;" :: "r"((uint32_t)(addr)), "r"((uint32_t)(cnt)) : "memory")
#define MBARRIER_EXPECT_TX(addr, bytes) \
    asm volatile("mbarrier.arrive.expect_tx.shared.b64 _, [%0], %1;" :: "r"((uint32_t)(addr)), "r"((uint32_t)(bytes)) : "memory")
#define MBARRIER_ARRIVE(addr) \
    asm volatile("mbarrier.arrive.shared.b64 _, [%0];" :: "r"((uint32_t)(addr)) : "memory")

#define MBARRIER_WAIT_PARITY(mbar_smem_addr, phase_parity) do { \
    uint32_t _mbar = (uint32_t)(mbar_smem_addr); \
    uint32_t _parity = (uint32_t)(phase_parity); \
    uint32_t _done; \
    asm volatile( \
        "{\n\t.reg .pred p;\n\t" \
        "mbarrier.try_wait.parity.acquire.cta.shared::cta.b64 p, [%1], %2;\n\t" \
        "selp.b32 %0, 1, 0, p;\n\t}" \
        : "=r"(_done) : "r"(_mbar), "r"(_parity) : "memory"); \
    if (!_done) { \
        asm volatile( \
            "{\n\t.reg .pred P1;\n\t" \
            "WAIT_LOOP_%=:\n\t" \
            "mbarrier.try_wait.parity.acquire.cta.shared::cta.b64 P1, [%0], %1, 0x989680;\n\t" \
            "@P1 bra.uni WAIT_DONE_%=;\n\t" \
            "bra.uni WAIT_LOOP_%=;\n\t" \
            "WAIT_DONE_%=:\n\t}" \
            :: "r"(_mbar), "r"(_parity) : "memory"); \
    } \
} while (0)

__device__ __forceinline__ void tma_load_2d(uint32_t smem_addr, const void* tmap,
                                            int32_t cx, int32_t cy, uint32_t mbar) {
    asm volatile(
        "cp.async.bulk.tensor.2d.shared::cta.global.tile.mbarrier::complete_tx::bytes "
        "[%0], [%1, {%2, %3}], [%4];"
        :: "r"(smem_addr), "l"(tmap), "r"(cx), "r"(cy), "r"(mbar) : "memory");
}

#define LDSM_X4(r0, r1, r2, r3, addr) \
    asm volatile("ldmatrix.sync.aligned.m8n8.x4.shared.b16 {%0,%1,%2,%3}, [%4];" \
        : "=r"(r0), "=r"(r1), "=r"(r2), "=r"(r3) : "r"(addr))
#define LDSM_X2(r0, r1, addr) \
    asm volatile("ldmatrix.sync.aligned.m8n8.x2.shared.b16 {%0,%1}, [%2];" \
        : "=r"(r0), "=r"(r1) : "r"(addr))

#define MMA_16816(d, a0, a1, a2, a3, b0, b1) \
    asm volatile("mma.sync.aligned.m16n8k16.row.col.f32.f16.f16.f32 " \
        "{%0,%1,%2,%3}, {%4,%5,%6,%7}, {%8,%9}, {%0,%1,%2,%3};" \
        : "+f"((d)[0]), "+f"((d)[1]), "+f"((d)[2]), "+f"((d)[3]) \
        : "r"(a0), "r"(a1), "r"(a2), "r"(a3), "r"(b0), "r"(b1))

// ---------------------------------------------------------------------------
// Prep kernels
// ---------------------------------------------------------------------------
__global__ void cdu_wconv_kernel(const float* __restrict__ Wsrc) {
    int i = blockIdx.x * blockDim.x + threadIdx.x;
    if (i < CDU_C * CDU_C)
        g_Wh[i] = __float2half(Wsrc[(size_t)i * 9 + 4]);   // W[o, c, 4, 0]
}

__global__ void cdu_init0_kernel(const float* __restrict__ fea, float* __restrict__ out) {
    int i = blockIdx.x * blockDim.x + threadIdx.x;   // i = c * NW + nw
    if (i < CDU_NB * KITERS) ((int*)g_flag)[i] = 0;  // reset flags (replay-safe)
    if (i < CDU_C * CDU_NW) {
        int c = i / CDU_NW, nw = i % CDU_NW;
        int n = nw / CDU_W, w = nw % CDU_W;
        size_t gi = (size_t)(n * CDU_C + c) * CDU_HW + w;  // h = 0
        float v = fea[gi];
        out[gi] = v;
        g_carry[0][(size_t)nw * CDU_C + c] = __float2half(v);  // carry v0 -> buf 0
    }
}

// ---------------------------------------------------------------------------
// Persistent dataflow kernel: all 94 steps, per-chunk flag dependencies.
// Grid (32 m-tiles, 4 n-tiles) = 128 CTAs; 160 threads:
//   warps 0-3: ldmatrix + mma.sync consumers (warp tile m32 x n48) -- R5
//   warp  4  : TMA producer; polls g_flag[nt][it] >= step per chunk
// ---------------------------------------------------------------------------
__global__ void __launch_bounds__(160, 1)
cdu_persist_kernel(const __grid_constant__ CUtensorMap mapA,
                   const __grid_constant__ CUtensorMap mapB0,
                   const __grid_constant__ CUtensorMap mapB1,
                   const float* __restrict__ fea,
                   float* __restrict__ out,
                   const float* __restrict__ bias)
{
    extern __shared__ __align__(1024) char smem[];
    uint32_t sb = smem_to_u32(smem);
    const int tid = threadIdx.x, wid = tid >> 5, lid = tid & 31;
    const int mt = blockIdx.x, nt = blockIdx.y;

    if (tid == 0) {
        for (int s = 0; s < STAGES; s++) {
            MBARRIER_INIT(sb + SMEM_BAR + s * 16, 1);       // full: 1 tx-arrive
            MBARRIER_INIT(sb + SMEM_BAR + s * 16 + 8, 4);   // empty: 4 consumer warps
        }
    }
    __syncthreads();

    if (wid == 4) {
        // ---- TMA producer: continuous stream of 94*32 chunks ----
        if (elect_one_pred()) {
            int s = 0, j = 0;
            for (int g = 0; g < NSTEPS * KITERS; g++) {
                const int step = g >> 5;          // KITERS == 32
                const int it = g & 31;
                // chunk it of step `step` needs m-tile `it` (same nt) to have
                // completed `step` steps (carry version `step` published)
                while (ld_acquire_gpu(&g_flag[nt][it]) < step) { }
                asm volatile("fence.proxy.async;" ::: "memory");
                if (j > 0) MBARRIER_WAIT_PARITY(sb + SMEM_BAR + s * 16 + 8, (j - 1) & 1);
                MBARRIER_EXPECT_TX(sb + SMEM_BAR + s * 16, A_STAGE_BYTES + B_STAGE_BYTES);
                tma_load_2d(sb + SMEM_A + s * A_STAGE_BYTES, &mapA,
                            it * KC, mt * M_TILE, sb + SMEM_BAR + s * 16);
                tma_load_2d(sb + SMEM_B + s * B_STAGE_BYTES,
                            (step & 1) ? (const void*)&mapB1 : (const void*)&mapB0,
                            it * KC, nt * N_TILE, sb + SMEM_BAR + s * 16);
                if (++s == STAGES) { s = 0; ++j; }
            }
        }
        return;
    }

    // ---- consumers: warps 0..3, warp tile m32 x n48 (verbatim R5) ----
    const int wm = wid & 1;        // m offset = wm*32
    const int wn = wid >> 1;       // n offset = wn*48
    const int r = lid >> 2, cq = (lid & 3) * 2;

    int cs = 0, cph = 0;           // persistent consumer stage cursor

    for (int step = 0; step < NSTEPS; step++) {
        const int h = (step < CDU_H - 1) ? (step + 1) : (2 * CDU_H - 3 - step);
        const float* xsl = ((step < CDU_H - 1) ? fea : (const float*)out) + h * CDU_W;
        float* osl = out + h * CDU_W;
        __half* cw = g_carry[(step + 1) & 1];   // carry write buffer

        float d[2][6][4];
        #pragma unroll
        for (int fm = 0; fm < 2; fm++)
            #pragma unroll
            for (int fn = 0; fn < 6; fn++)
                #pragma unroll
                for (int q = 0; q < 4; q++) d[fm][fn][q] = 0.f;

        for (int it = 0; it < KITERS; it++) {
            MBARRIER_WAIT_PARITY(sb + SMEM_BAR + cs * 16, cph);
            const uint32_t aBase = sb + SMEM_A + cs * A_STAGE_BYTES;
            const uint32_t bBase = sb + SMEM_B + cs * B_STAGE_BYTES;
            #pragma unroll
            for (int kk = 0; kk < 4; kk++) {
                uint32_t a[2][4];
                #pragma unroll
                for (int fm = 0; fm < 2; fm++) {
                    int row = wm * 32 + fm * 16 + (lid & 15);
                    int col = kk * 32 + ((lid >> 4) << 4);
                    uint32_t off = row * 128 + (col ^ ((row & 7) << 4));  // SW128
                    LDSM_X4(a[fm][0], a[fm][1], a[fm][2], a[fm][3], aBase + off);
                }
                #pragma unroll
                for (int fn = 0; fn < 6; fn++) {
                    int row = wn * 48 + fn * 8 + (lid & 7);
                    int col = kk * 32 + (((lid >> 3) & 1) << 4);
                    uint32_t off = row * 128 + (col ^ ((row & 7) << 4));  // SW128
                    uint32_t b0, b1;
                    LDSM_X2(b0, b1, bBase + off);
                    MMA_16816(d[0][fn], a[0][0], a[0][1], a[0][2], a[0][3], b0, b1);
                    MMA_16816(d[1][fn], a[1][0], a[1][1], a[1][2], a[1][3], b0, b1);
                }
            }
            if (elect_one_pred()) MBARRIER_ARRIVE(sb + SMEM_BAR + cs * 16 + 8);
            if (++cs == STAGES) { cs = 0; cph ^= 1; }
        }

        // ---- epilogue (R5 layout): out + carry (ping-pong buffer) ----
        #pragma unroll
        for (int fm = 0; fm < 2; fm++) {
            const int c0 = mt * M_TILE + wm * 32 + fm * 16 + r;
            const int c1 = c0 + 8;
            const float bv0 = bias[c0], bv1 = bias[c1];
            const float* xr0 = xsl + (size_t)(nt * CDU_C + c0) * CDU_HW;
            const float* xr1 = xsl + (size_t)(nt * CDU_C + c1) * CDU_HW;
            float* or0 = osl + (size_t)(nt * CDU_C + c0) * CDU_HW;
            float* or1 = osl + (size_t)(nt * CDU_C + c1) * CDU_HW;
            #pragma unroll
            for (int fn = 0; fn < 6; fn++) {
                const int w0 = wn * 48 + fn * 8 + cq;
                float2 xv0 = *reinterpret_cast<const float2*>(xr0 + w0);
                float2 xv1 = *reinterpret_cast<const float2*>(xr1 + w0);
                float2 o0, o1;
                o0.x = fmaxf(d[fm][fn][0] + bv0, 0.f) + xv0.x;
                o0.y = fmaxf(d[fm][fn][1] + bv0, 0.f) + xv0.y;
                o1.x = fmaxf(d[fm][fn][2] + bv1, 0.f) + xv1.x;
                o1.y = fmaxf(d[fm][fn][3] + bv1, 0.f) + xv1.y;
                *reinterpret_cast<float2*>(or0 + w0) = o0;
                *reinterpret_cast<float2*>(or1 + w0) = o1;
                const size_t nwb = (size_t)(nt * N_TILE + w0);
                cw[nwb * CDU_C + c0]       = __float2half(o0.x);
                cw[(nwb + 1) * CDU_C + c0] = __float2half(o0.y);
                cw[nwb * CDU_C + c1]       = __float2half(o1.x);
                cw[(nwb + 1) * CDU_C + c1] = __float2half(o1.y);
            }
        }

        // ---- publish progress: all consumer stores -> flag[nt][mt] = step+1
        asm volatile("bar.sync 2, 128;" ::: "memory");
        if (tid == 0) {
            __threadfence();
            atomicExch(&g_flag[nt][mt], step + 1);
        }
        // consumers proceed; next step's data gated by full-mbarriers
    }
}

// ---------------------------------------------------------------------------
// Host
// ---------------------------------------------------------------------------
typedef CUresult (*cdu_encode_fn)(CUtensorMap*, CUtensorMapDataType, cuuint32_t, void*,
                                  const cuuint64_t*, const cuuint64_t*, const cuuint32_t*,
                                  const cuuint32_t*, CUtensorMapInterleave, CUtensorMapSwizzle,
                                  CUtensorMapL2promotion, CUtensorMapFloatOOBfill);

extern "C" void kernel_launch(void* const* d_in, const int* in_sizes, int n_in,
                              void* d_out, int out_size) {
    const float* fea = (const float*)d_in[0];
    const float* Wt  = (const float*)d_in[1];
    const float* b   = (const float*)d_in[2];
    float* out = (float*)d_out;

    void* whp = nullptr;  cudaGetSymbolAddress(&whp, g_Wh);
    void* cp  = nullptr;  cudaGetSymbolAddress(&cp, g_carry);
    __half* cb0 = (__half*)cp;
    __half* cb1 = cb0 + (size_t)CDU_NW * CDU_C;

    cdu_encode_fn enc = nullptr;
    cudaDriverEntryPointQueryResult qr;
    cudaGetDriverEntryPointByVersion("cuTensorMapEncodeTiled", (void**)&enc, 12000,
                                     cudaEnableDefault, &qr);

    CUtensorMap mapA, mapB0, mapB1;
    {
        cuuint64_t dimsA[2]  = {CDU_C, CDU_C};
        cuuint64_t stride[1] = {CDU_C * sizeof(__half)};
        cuuint32_t boxA[2]   = {KC, M_TILE};
        cuuint32_t es[2]     = {1, 1};
        enc(&mapA, CU_TENSOR_MAP_DATA_TYPE_FLOAT16, 2, whp, dimsA, stride, boxA, es,
            CU_TENSOR_MAP_INTERLEAVE_NONE, CU_TENSOR_MAP_SWIZZLE_128B,
            CU_TENSOR_MAP_L2_PROMOTION_L2_128B, CU_TENSOR_MAP_FLOAT_OOB_FILL_NONE);
        cuuint64_t dimsB[2]  = {CDU_C, CDU_NW};
        cuuint32_t boxB[2]   = {KC, N_TILE};
        enc(&mapB0, CU_TENSOR_MAP_DATA_TYPE_FLOAT16, 2, cb0, dimsB, stride, boxB, es,
            CU_TENSOR_MAP_INTERLEAVE_NONE, CU_TENSOR_MAP_SWIZZLE_128B,
            CU_TENSOR_MAP_L2_PROMOTION_L2_128B, CU_TENSOR_MAP_FLOAT_OOB_FILL_NONE);
        enc(&mapB1, CU_TENSOR_MAP_DATA_TYPE_FLOAT16, 2, cb1, dimsB, stride, boxB, es,
            CU_TENSOR_MAP_INTERLEAVE_NONE, CU_TENSOR_MAP_SWIZZLE_128B,
            CU_TENSOR_MAP_L2_PROMOTION_L2_128B, CU_TENSOR_MAP_FLOAT_OOB_FILL_NONE);
    }

    cudaFuncSetAttribute(cdu_persist_kernel, cudaFuncAttributeMaxDynamicSharedMemorySize, SMEM_TOTAL);

    cdu_wconv_kernel<<<(CDU_C * CDU_C + 255) / 256, 256>>>(Wt);
    cdu_init0_kernel<<<(CDU_C * CDU_NW + 255) / 256, 256>>>(fea, out);

    dim3 grid(CDU_C / M_TILE, CDU_NW / N_TILE);   // (32, 4) = 128 CTAs, 1 wave
    cdu_persist_kernel<<<grid, 160, SMEM_TOTAL>>>(mapA, mapB0, mapB1, fea, out, b);
}

// round 14
// speedup vs baseline: 2.0097x; 2.0097x over previous
#include <cuda_runtime.h>
#include <cuda.h>
#include <cuda_fp16.h>
#include <cstdint>

// ============================================================================
// convDU: bidirectional recurrent conv along H.
//   step: y = relu(Wm @ carry + b) + x     (Wm = W[:,:,4,0], 2048x2048)
// 94 serial GEMM steps of [2048x2048]x[2048x384].
// Base-ISA tensor cores: TMA+mbarrier pipeline -> ldmatrix -> mma.sync
// m16n8k16 f16, fp32 accum.
// Status: step mainloop measured at ~97% of the sm_103a legacy-mma.sync
// throughput wall (~512 MAC/cyc/SM), invariant to schedule (R7,R9),
// accumulator type (R11), and inter-step sync structure (R10,R12,R13).
// R14 = validated R5 step kernel (best: 1230.8us) + single merged prep
// kernel (wconv + init0 in one launch; init0's small work hides in the
// DRAM-bound W conversion).
// ============================================================================

#define CDU_C   2048
#define CDU_NB  4
#define CDU_H   48
#define CDU_W   96
#define CDU_NW  (CDU_NB * CDU_W)     // 384
#define CDU_HW  (CDU_H * CDU_W)      // 4608

#define M_TILE  64
#define N_TILE  96                   // one image's w-columns per CTA
#define KC      64                   // k elems per stage (64 * 2B = 128B SW128 row)
#define KITERS  (CDU_C / KC)         // 32
#define STAGES  6

#define A_STAGE_BYTES (M_TILE * 128)     // 8192
#define B_STAGE_BYTES (N_TILE * 128)     // 12288
#define SMEM_BAR      64                 // full[s] @ 64+16s, empty[s] @ +8
#define SMEM_A        1024
#define SMEM_B        (SMEM_A + STAGES * A_STAGE_BYTES)     // 50176
#define SMEM_TOTAL    (SMEM_B + STAGES * B_STAGE_BYTES)     // 123904

// fp16 scratch: converted weight matrix + recurrent carry (K-major [nw][c])
__device__ __align__(16) __half g_Wh[CDU_C * CDU_C];
__device__ __align__(16) __half g_carry[CDU_NW * CDU_C];

// ---------------------------------------------------------------------------
// PTX helpers (base-ISA only)
// ---------------------------------------------------------------------------
__device__ __forceinline__ uint32_t elect_one_pred() {
    uint32_t pred;
    asm volatile(
        "{\n\t.reg .pred p;\n\telect.sync _|p, 0xFFFFFFFF;\n\t"
        "selp.b32 %0, 1, 0, p;\n\t}" : "=r"(pred));
    return pred;
}
__device__ __forceinline__ uint32_t smem_to_u32(const void* p) {
    uint32_t a;
    asm("{ .reg .u64 t; cvta.to.shared.u64 t, %1; cvt.u32.u64 %0, t; }" : "=r"(a) : "l"(p));
    return a;
}

#define MBARRIER_INIT(addr, cnt) \
    asm volatile("mbarrier.init.shared.b64 [%0], %1;" :: "r"((uint32_t)(addr)), "r"((uint32_t)(cnt)) : "memory")
#define MBARRIER_EXPECT_TX(addr, bytes) \
    asm volatile("mbarrier.arrive.expect_tx.shared.b64 _, [%0], %1;" :: "r"((uint32_t)(addr)), "r"((uint32_t)(bytes)) : "memory")
#define MBARRIER_ARRIVE(addr) \
    asm volatile("mbarrier.arrive.shared.b64 _, [%0];" :: "r"((uint32_t)(addr)) : "memory")

#define MBARRIER_WAIT_PARITY(mbar_smem_addr, phase_parity) do { \
    uint32_t _mbar = (uint32_t)(mbar_smem_addr); \
    uint32_t _parity = (uint32_t)(phase_parity); \
    uint32_t _done; \
    asm volatile( \
        "{\n\t.reg .pred p;\n\t" \
        "mbarrier.try_wait.parity.acquire.cta.shared::cta.b64 p, [%1], %2;\n\t" \
        "selp.b32 %0, 1, 0, p;\n\t}" \
        : "=r"(_done) : "r"(_mbar), "r"(_parity) : "memory"); \
    if (!_done) { \
        asm volatile( \
            "{\n\t.reg .pred P1;\n\t" \
            "WAIT_LOOP_%=:\n\t" \
            "mbarrier.try_wait.parity.acquire.cta.shared::cta.b64 P1, [%0], %1, 0x989680;\n\t" \
            "@P1 bra.uni WAIT_DONE_%=;\n\t" \
            "bra.uni WAIT_LOOP_%=;\n\t" \
            "WAIT_DONE_%=:\n\t}" \
            :: "r"(_mbar), "r"(_parity) : "memory"); \
    } \
} while (0)

__device__ __forceinline__ void tma_load_2d(uint32_t smem_addr, const void* tmap,
                                            int32_t cx, int32_t cy, uint32_t mbar) {
    asm volatile(
        "cp.async.bulk.tensor.2d.shared::cta.global.tile.mbarrier::complete_tx::bytes "
        "[%0], [%1, {%2, %3}], [%4];"
        :: "r"(smem_addr), "l"(tmap), "r"(cx), "r"(cy), "r"(mbar) : "memory");
}

#define LDSM_X4(r0, r1, r2, r3, addr) \
    asm volatile("ldmatrix.sync.aligned.m8n8.x4.shared.b16 {%0,%1,%2,%3}, [%4];" \
        : "=r"(r0), "=r"(r1), "=r"(r2), "=r"(r3) : "r"(addr))
#define LDSM_X2(r0, r1, addr) \
    asm volatile("ldmatrix.sync.aligned.m8n8.x2.shared.b16 {%0,%1}, [%2];" \
        : "=r"(r0), "=r"(r1) : "r"(addr))

#define MMA_16816(d, a0, a1, a2, a3, b0, b1) \
    asm volatile("mma.sync.aligned.m16n8k16.row.col.f32.f16.f16.f32 " \
        "{%0,%1,%2,%3}, {%4,%5,%6,%7}, {%8,%9}, {%0,%1,%2,%3};" \
        : "+f"((d)[0]), "+f"((d)[1]), "+f"((d)[2]), "+f"((d)[3]) \
        : "r"(a0), "r"(a1), "r"(a2), "r"(a3), "r"(b0), "r"(b1))

// ---------------------------------------------------------------------------
// Merged prep kernel: W conversion + h=0 init in ONE launch.
// The init part (786K elems) hides inside the DRAM-bound W conversion
// (4.2M strided elems, ~134MB of sector traffic).
// ---------------------------------------------------------------------------
#define PREP_BLOCKS  1184            // 148 SMs x 8 blocks
#define PREP_THREADS 256

__global__ void __launch_bounds__(PREP_THREADS)
cdu_prep_kernel(const float* __restrict__ Wsrc,
                const float* __restrict__ fea,
                float* __restrict__ out) {
    const int gstride = PREP_BLOCKS * PREP_THREADS;
    int g = blockIdx.x * PREP_THREADS + threadIdx.x;
    // init0: carry/out for h = 0
    for (int i = g; i < CDU_C * CDU_NW; i += gstride) {
        int c = i / CDU_NW, nw = i % CDU_NW;
        int n = nw / CDU_W, w = nw % CDU_W;
        size_t gi = (size_t)(n * CDU_C + c) * CDU_HW + w;  // h = 0
        float v = fea[gi];
        out[gi] = v;
        g_carry[(size_t)nw * CDU_C + c] = __float2half(v);
    }
    // wconv: W[o, c, 4, 0] -> fp16
    for (int i = g; i < CDU_C * CDU_C; i += gstride)
        g_Wh[i] = __float2half(Wsrc[(size_t)i * 9 + 4]);
}

// ---------------------------------------------------------------------------
// One recurrence step: D = relu(Wm @ carry + b) + x ; out/carry <- D
// Grid (32 m-tiles, 4 n-tiles) = 128 CTAs; 160 threads:
//   warps 0-3: ldmatrix + mma.sync consumers (warp tile m32 x n48)
//   warp  4  : TMA producer
// (byte-identical to validated R5)
// ---------------------------------------------------------------------------
__global__ void __launch_bounds__(160, 1)
cdu_step_kernel(const __grid_constant__ CUtensorMap mapA,
                const __grid_constant__ CUtensorMap mapB,
                const float* __restrict__ xsl,      // x slice base (already + h*W)
                float* __restrict__ osl,            // out slice base (already + h*W)
                const float* __restrict__ bias)
{
    extern __shared__ __align__(1024) char smem[];
    uint32_t sb = smem_to_u32(smem);
    const int tid = threadIdx.x, wid = tid >> 5, lid = tid & 31;
    const int mt = blockIdx.x, nt = blockIdx.y;

    if (tid == 0) {
        for (int s = 0; s < STAGES; s++) {
            MBARRIER_INIT(sb + SMEM_BAR + s * 16, 1);       // full: 1 tx-arrive
            MBARRIER_INIT(sb + SMEM_BAR + s * 16 + 8, 4);   // empty: 4 consumer warps
        }
    }
    __syncthreads();

    if (wid == 4) {
        // ---- TMA producer ----
        if (elect_one_pred()) {
            int s = 0, j = 0;
            for (int it = 0; it < KITERS; it++) {
                if (j > 0) MBARRIER_WAIT_PARITY(sb + SMEM_BAR + s * 16 + 8, (j - 1) & 1);
                MBARRIER_EXPECT_TX(sb + SMEM_BAR + s * 16, A_STAGE_BYTES + B_STAGE_BYTES);
                tma_load_2d(sb + SMEM_A + s * A_STAGE_BYTES, &mapA,
                            it * KC, mt * M_TILE, sb + SMEM_BAR + s * 16);
                tma_load_2d(sb + SMEM_B + s * B_STAGE_BYTES, &mapB,
                            it * KC, nt * N_TILE, sb + SMEM_BAR + s * 16);
                if (++s == STAGES) { s = 0; ++j; }
            }
        }
        return;
    }

    // ---- consumers: warps 0..3, warp tile m32 x n48 ----
    const int wm = wid & 1;        // m offset = wm*32
    const int wn = wid >> 1;       // n offset = wn*48

    float d[2][6][4];
    #pragma unroll
    for (int fm = 0; fm < 2; fm++)
        #pragma unroll
        for (int fn = 0; fn < 6; fn++)
            #pragma unroll
            for (int q = 0; q < 4; q++) d[fm][fn][q] = 0.f;

    {
        int s = 0, ph = 0;
        for (int it = 0; it < KITERS; it++) {
            MBARRIER_WAIT_PARITY(sb + SMEM_BAR + s * 16, ph);
            const uint32_t aBase = sb + SMEM_A + s * A_STAGE_BYTES;
            const uint32_t bBase = sb + SMEM_B + s * B_STAGE_BYTES;
            #pragma unroll
            for (int kk = 0; kk < 4; kk++) {
                uint32_t a[2][4];
                #pragma unroll
                for (int fm = 0; fm < 2; fm++) {
                    int row = wm * 32 + fm * 16 + (lid & 15);
                    int col = kk * 32 + ((lid >> 4) << 4);
                    uint32_t off = row * 128 + (col ^ ((row & 7) << 4));  // SW128
                    LDSM_X4(a[fm][0], a[fm][1], a[fm][2], a[fm][3], aBase + off);
                }
                #pragma unroll
                for (int fn = 0; fn < 6; fn++) {
                    int row = wn * 48 + fn * 8 + (lid & 7);
                    int col = kk * 32 + (((lid >> 3) & 1) << 4);
                    uint32_t off = row * 128 + (col ^ ((row & 7) << 4));  // SW128
                    uint32_t b0, b1;
                    LDSM_X2(b0, b1, bBase + off);
                    MMA_16816(d[0][fn], a[0][0], a[0][1], a[0][2], a[0][3], b0, b1);
                    MMA_16816(d[1][fn], a[1][0], a[1][1], a[1][2], a[1][3], b0, b1);
                }
            }
            if (elect_one_pred()) MBARRIER_ARRIVE(sb + SMEM_BAR + s * 16 + 8);
            if (++s == STAGES) { s = 0; ph ^= 1; }
        }
    }

    // ---- epilogue: D frag rows = out channel c, cols = w (2 consecutive) ----
    const int r = lid >> 2, cq = (lid & 3) * 2;
    #pragma unroll
    for (int fm = 0; fm < 2; fm++) {
        const int c0 = mt * M_TILE + wm * 32 + fm * 16 + r;
        const int c1 = c0 + 8;
        const float bv0 = bias[c0], bv1 = bias[c1];
        const float* xr0 = xsl + (size_t)(nt * CDU_C + c0) * CDU_HW;
        const float* xr1 = xsl + (size_t)(nt * CDU_C + c1) * CDU_HW;
        float* or0 = osl + (size_t)(nt * CDU_C + c0) * CDU_HW;
        float* or1 = osl + (size_t)(nt * CDU_C + c1) * CDU_HW;
        #pragma unroll
        for (int fn = 0; fn < 6; fn++) {
            const int w0 = wn * 48 + fn * 8 + cq;
            float2 xv0 = *reinterpret_cast<const float2*>(xr0 + w0);
            float2 xv1 = *reinterpret_cast<const float2*>(xr1 + w0);
            float2 o0, o1;
            o0.x = fmaxf(d[fm][fn][0] + bv0, 0.f) + xv0.x;
            o0.y = fmaxf(d[fm][fn][1] + bv0, 0.f) + xv0.y;
            o1.x = fmaxf(d[fm][fn][2] + bv1, 0.f) + xv1.x;
            o1.y = fmaxf(d[fm][fn][3] + bv1, 0.f) + xv1.y;
            *reinterpret_cast<float2*>(or0 + w0) = o0;
            *reinterpret_cast<float2*>(or1 + w0) = o1;
            // carry (fp16, K-major [nw][c]) for the next step's B operand
            const size_t nwb = (size_t)(nt * N_TILE + w0);
            g_carry[nwb * CDU_C + c0]       = __float2half(o0.x);
            g_carry[(nwb + 1) * CDU_C + c0] = __float2half(o0.y);
            g_carry[nwb * CDU_C + c1]       = __float2half(o1.x);
            g_carry[(nwb + 1) * CDU_C + c1] = __float2half(o1.y);
        }
    }
}

// ---------------------------------------------------------------------------
// Host
// ---------------------------------------------------------------------------
typedef CUresult (*cdu_encode_fn)(CUtensorMap*, CUtensorMapDataType, cuuint32_t, void*,
                                  const cuuint64_t*, const cuuint64_t*, const cuuint32_t*,
                                  const cuuint32_t*, CUtensorMapInterleave, CUtensorMapSwizzle,
                                  CUtensorMapL2promotion, CUtensorMapFloatOOBfill);

extern "C" void kernel_launch(void* const* d_in, const int* in_sizes, int n_in,
                              void* d_out, int out_size) {
    const float* fea = (const float*)d_in[0];
    const float* Wt  = (const float*)d_in[1];
    const float* b   = (const float*)d_in[2];
    float* out = (float*)d_out;

    void* whp = nullptr;  cudaGetSymbolAddress(&whp, g_Wh);
    void* cp  = nullptr;  cudaGetSymbolAddress(&cp, g_carry);

    cdu_encode_fn enc = nullptr;
    cudaDriverEntryPointQueryResult qr;
    cudaGetDriverEntryPointByVersion("cuTensorMapEncodeTiled", (void**)&enc, 12000,
                                     cudaEnableDefault, &qr);

    CUtensorMap mapA, mapB;
    {
        cuuint64_t dimsA[2]  = {CDU_C, CDU_C};
        cuuint64_t stride[1] = {CDU_C * sizeof(__half)};
        cuuint32_t boxA[2]   = {KC, M_TILE};
        cuuint32_t es[2]     = {1, 1};
        enc(&mapA, CU_TENSOR_MAP_DATA_TYPE_FLOAT16, 2, whp, dimsA, stride, boxA, es,
            CU_TENSOR_MAP_INTERLEAVE_NONE, CU_TENSOR_MAP_SWIZZLE_128B,
            CU_TENSOR_MAP_L2_PROMOTION_L2_128B, CU_TENSOR_MAP_FLOAT_OOB_FILL_NONE);
        cuuint64_t dimsB[2]  = {CDU_C, CDU_NW};
        cuuint32_t boxB[2]   = {KC, N_TILE};
        enc(&mapB, CU_TENSOR_MAP_DATA_TYPE_FLOAT16, 2, cp, dimsB, stride, boxB, es,
            CU_TENSOR_MAP_INTERLEAVE_NONE, CU_TENSOR_MAP_SWIZZLE_128B,
            CU_TENSOR_MAP_L2_PROMOTION_L2_128B, CU_TENSOR_MAP_FLOAT_OOB_FILL_NONE);
    }

    cudaFuncSetAttribute(cdu_step_kernel, cudaFuncAttributeMaxDynamicSharedMemorySize, SMEM_TOTAL);

    cdu_prep_kernel<<<PREP_BLOCKS, PREP_THREADS>>>(Wt, fea, out);

    dim3 grid(CDU_C / M_TILE, CDU_NW / N_TILE);   // (32, 4)
    // forward scan: h = 1..47
    for (int h = 1; h < CDU_H; h++)
        cdu_step_kernel<<<grid, 160, SMEM_TOTAL>>>(mapA, mapB, fea + h * CDU_W, out + h * CDU_W, b);
    // backward scan: h = 46..0 (x = down[h] staged in out)
    for (int h = CDU_H - 2; h >= 0; h--)
        cdu_step_kernel<<<grid, 160, SMEM_TOTAL>>>(mapA, mapB, out + h * CDU_W, out + h * CDU_W, b);
}

// round 15
// speedup vs baseline: 2.1447x; 1.0672x over previous
#include <cuda_runtime.h>
#include <cuda.h>
#include <cuda_fp16.h>
#include <cstdint>

// ============================================================================
// convDU: bidirectional recurrent conv along H.
//   step: y = relu(Wm @ carry + b) + x     (Wm = W[:,:,4,0], 2048x2048)
// 94 serial GEMM steps of [2048x2048]x[2048x384].
// Base-ISA tensor cores: TMA+mbarrier pipeline -> ldmatrix -> mma.sync
// m16n8k16 f16, fp32 accum. Step mainloop is at ~99% of the measured
// legacy-mma pace (227cyc/k16/SMSP), schedule-invariant (R5/R7/R9/R11).
// R15: halve the per-step synchronization count. Each pipeline stage now
// carries TWO K-chunks (K=128: 2 TMA loads per operand, one mbarrier,
// expect_tx=40KB), STAGES 6->3 (same smem footprint, same byte look-ahead).
// Consumers wait/arrive 16x per step instead of 32x. Fragments, MMA order,
// epilogue byte-identical to validated R5/R14 (best: 1230.8us).
// ============================================================================

#define CDU_C   2048
#define CDU_NB  4
#define CDU_H   48
#define CDU_W   96
#define CDU_NW  (CDU_NB * CDU_W)     // 384
#define CDU_HW  (CDU_H * CDU_W)      // 4608

#define M_TILE  64
#define N_TILE  96                   // one image's w-columns per CTA
#define KC      64                   // k elems per TMA box (128B SW128 row)
#define CPS     2                    // K-chunks per pipeline stage (K=128/stage)
#define SITERS  (CDU_C / (KC * CPS)) // 16 stage-iterations
#define STAGES  3

#define A_CHUNK_BYTES (M_TILE * 128)             // 8192
#define B_CHUNK_BYTES (N_TILE * 128)             // 12288
#define A_STAGE_BYTES (CPS * A_CHUNK_BYTES)      // 16384
#define B_STAGE_BYTES (CPS * B_CHUNK_BYTES)      // 24576
#define SMEM_BAR      64                         // full[s] @ 64+16s, empty[s] @ +8
#define SMEM_A        1024
#define SMEM_B        (SMEM_A + STAGES * A_STAGE_BYTES)     // 50176
#define SMEM_TOTAL    (SMEM_B + STAGES * B_STAGE_BYTES)     // 123904

// fp16 scratch: converted weight matrix + recurrent carry (K-major [nw][c])
__device__ __align__(16) __half g_Wh[CDU_C * CDU_C];
__device__ __align__(16) __half g_carry[CDU_NW * CDU_C];

// ---------------------------------------------------------------------------
// PTX helpers (base-ISA only)
// ---------------------------------------------------------------------------
__device__ __forceinline__ uint32_t elect_one_pred() {
    uint32_t pred;
    asm volatile(
        "{\n\t.reg .pred p;\n\telect.sync _|p, 0xFFFFFFFF;\n\t"
        "selp.b32 %0, 1, 0, p;\n\t}" : "=r"(pred));
    return pred;
}
__device__ __forceinline__ uint32_t smem_to_u32(const void* p) {
    uint32_t a;
    asm("{ .reg .u64 t; cvta.to.shared.u64 t, %1; cvt.u32.u64 %0, t; }" : "=r"(a) : "l"(p));
    return a;
}

#define MBARRIER_INIT(addr, cnt) \
    asm volatile("mbarrier.init.shared.b64 [%0], %1;" :: "r"((uint32_t)(addr)), "r"((uint32_t)(cnt)) : "memory")
#define MBARRIER_EXPECT_TX(addr, bytes) \
    asm volatile("mbarrier.arrive.expect_tx.shared.b64 _, [%0], %1;" :: "r"((uint32_t)(addr)), "r"((uint32_t)(bytes)) : "memory")
#define MBARRIER_ARRIVE(addr) \
    asm volatile("mbarrier.arrive.shared.b64 _, [%0];" :: "r"((uint32_t)(addr)) : "memory")

#define MBARRIER_WAIT_PARITY(mbar_smem_addr, phase_parity) do { \
    uint32_t _mbar = (uint32_t)(mbar_smem_addr); \
    uint32_t _parity = (uint32_t)(phase_parity); \
    uint32_t _done; \
    asm volatile( \
        "{\n\t.reg .pred p;\n\t" \
        "mbarrier.try_wait.parity.acquire.cta.shared::cta.b64 p, [%1], %2;\n\t" \
        "selp.b32 %0, 1, 0, p;\n\t}" \
        : "=r"(_done) : "r"(_mbar), "r"(_parity) : "memory"); \
    if (!_done) { \
        asm volatile( \
            "{\n\t.reg .pred P1;\n\t" \
            "WAIT_LOOP_%=:\n\t" \
            "mbarrier.try_wait.parity.acquire.cta.shared::cta.b64 P1, [%0], %1, 0x989680;\n\t" \
            "@P1 bra.uni WAIT_DONE_%=;\n\t" \
            "bra.uni WAIT_LOOP_%=;\n\t" \
            "WAIT_DONE_%=:\n\t}" \
            :: "r"(_mbar), "r"(_parity) : "memory"); \
    } \
} while (0)

__device__ __forceinline__ void tma_load_2d(uint32_t smem_addr, const void* tmap,
                                            int32_t cx, int32_t cy, uint32_t mbar) {
    asm volatile(
        "cp.async.bulk.tensor.2d.shared::cta.global.tile.mbarrier::complete_tx::bytes "
        "[%0], [%1, {%2, %3}], [%4];"
        :: "r"(smem_addr), "l"(tmap), "r"(cx), "r"(cy), "r"(mbar) : "memory");
}

#define LDSM_X4(r0, r1, r2, r3, addr) \
    asm volatile("ldmatrix.sync.aligned.m8n8.x4.shared.b16 {%0,%1,%2,%3}, [%4];" \
        : "=r"(r0), "=r"(r1), "=r"(r2), "=r"(r3) : "r"(addr))
#define LDSM_X2(r0, r1, addr) \
    asm volatile("ldmatrix.sync.aligned.m8n8.x2.shared.b16 {%0,%1}, [%2];" \
        : "=r"(r0), "=r"(r1) : "r"(addr))

#define MMA_16816(d, a0, a1, a2, a3, b0, b1) \
    asm volatile("mma.sync.aligned.m16n8k16.row.col.f32.f16.f16.f32 " \
        "{%0,%1,%2,%3}, {%4,%5,%6,%7}, {%8,%9}, {%0,%1,%2,%3};" \
        : "+f"((d)[0]), "+f"((d)[1]), "+f"((d)[2]), "+f"((d)[3]) \
        : "r"(a0), "r"(a1), "r"(a2), "r"(a3), "r"(b0), "r"(b1))

// ---------------------------------------------------------------------------
// Merged prep kernel (R14): W conversion + h=0 init in ONE launch.
// ---------------------------------------------------------------------------
#define PREP_BLOCKS  1184            // 148 SMs x 8 blocks
#define PREP_THREADS 256

__global__ void __launch_bounds__(PREP_THREADS)
cdu_prep_kernel(const float* __restrict__ Wsrc,
                const float* __restrict__ fea,
                float* __restrict__ out) {
    const int gstride = PREP_BLOCKS * PREP_THREADS;
    int g = blockIdx.x * PREP_THREADS + threadIdx.x;
    // init0: carry/out for h = 0
    for (int i = g; i < CDU_C * CDU_NW; i += gstride) {
        int c = i / CDU_NW, nw = i % CDU_NW;
        int n = nw / CDU_W, w = nw % CDU_W;
        size_t gi = (size_t)(n * CDU_C + c) * CDU_HW + w;  // h = 0
        float v = fea[gi];
        out[gi] = v;
        g_carry[(size_t)nw * CDU_C + c] = __float2half(v);
    }
    // wconv: W[o, c, 4, 0] -> fp16
    for (int i = g; i < CDU_C * CDU_C; i += gstride)
        g_Wh[i] = __float2half(Wsrc[(size_t)i * 9 + 4]);
}

// ---------------------------------------------------------------------------
// One recurrence step: D = relu(Wm @ carry + b) + x ; out/carry <- D
// Grid (32 m-tiles, 4 n-tiles) = 128 CTAs; 160 threads:
//   warps 0-3: ldmatrix + mma.sync consumers (warp tile m32 x n48)
//   warp  4  : TMA producer (2 chunks = 4 TMA loads per stage)
// ---------------------------------------------------------------------------
__global__ void __launch_bounds__(160, 1)
cdu_step_kernel(const __grid_constant__ CUtensorMap mapA,
                const __grid_constant__ CUtensorMap mapB,
                const float* __restrict__ xsl,      // x slice base (already + h*W)
                float* __restrict__ osl,            // out slice base (already + h*W)
                const float* __restrict__ bias)
{
    extern __shared__ __align__(1024) char smem[];
    uint32_t sb = smem_to_u32(smem);
    const int tid = threadIdx.x, wid = tid >> 5, lid = tid & 31;
    const int mt = blockIdx.x, nt = blockIdx.y;

    if (tid == 0) {
        for (int s = 0; s < STAGES; s++) {
            MBARRIER_INIT(sb + SMEM_BAR + s * 16, 1);       // full: 1 tx-arrive
            MBARRIER_INIT(sb + SMEM_BAR + s * 16 + 8, 4);   // empty: 4 consumer warps
        }
    }
    __syncthreads();

    if (wid == 4) {
        // ---- TMA producer: one mbarrier per 2-chunk stage ----
        if (elect_one_pred()) {
            int s = 0, j = 0;
            for (int it = 0; it < SITERS; it++) {
                if (j > 0) MBARRIER_WAIT_PARITY(sb + SMEM_BAR + s * 16 + 8, (j - 1) & 1);
                MBARRIER_EXPECT_TX(sb + SMEM_BAR + s * 16, A_STAGE_BYTES + B_STAGE_BYTES);
                const int k0 = it * (KC * CPS);
                #pragma unroll
                for (int c = 0; c < CPS; c++) {
                    tma_load_2d(sb + SMEM_A + s * A_STAGE_BYTES + c * A_CHUNK_BYTES, &mapA,
                                k0 + c * KC, mt * M_TILE, sb + SMEM_BAR + s * 16);
                    tma_load_2d(sb + SMEM_B + s * B_STAGE_BYTES + c * B_CHUNK_BYTES, &mapB,
                                k0 + c * KC, nt * N_TILE, sb + SMEM_BAR + s * 16);
                }
                if (++s == STAGES) { s = 0; ++j; }
            }
        }
        return;
    }

    // ---- consumers: warps 0..3, warp tile m32 x n48 ----
    const int wm = wid & 1;        // m offset = wm*32
    const int wn = wid >> 1;       // n offset = wn*48

    float d[2][6][4];
    #pragma unroll
    for (int fm = 0; fm < 2; fm++)
        #pragma unroll
        for (int fn = 0; fn < 6; fn++)
            #pragma unroll
            for (int q = 0; q < 4; q++) d[fm][fn][q] = 0.f;

    {
        int s = 0, ph = 0;
        for (int it = 0; it < SITERS; it++) {
            MBARRIER_WAIT_PARITY(sb + SMEM_BAR + s * 16, ph);
            #pragma unroll
            for (int c = 0; c < CPS; c++) {
                const uint32_t aBase = sb + SMEM_A + s * A_STAGE_BYTES + c * A_CHUNK_BYTES;
                const uint32_t bBase = sb + SMEM_B + s * B_STAGE_BYTES + c * B_CHUNK_BYTES;
                #pragma unroll
                for (int kk = 0; kk < 4; kk++) {
                    uint32_t a[2][4];
                    #pragma unroll
                    for (int fm = 0; fm < 2; fm++) {
                        int row = wm * 32 + fm * 16 + (lid & 15);
                        int col = kk * 32 + ((lid >> 4) << 4);
                        uint32_t off = row * 128 + (col ^ ((row & 7) << 4));  // SW128
                        LDSM_X4(a[fm][0], a[fm][1], a[fm][2], a[fm][3], aBase + off);
                    }
                    #pragma unroll
                    for (int fn = 0; fn < 6; fn++) {
                        int row = wn * 48 + fn * 8 + (lid & 7);
                        int col = kk * 32 + (((lid >> 3) & 1) << 4);
                        uint32_t off = row * 128 + (col ^ ((row & 7) << 4));  // SW128
                        uint32_t b0, b1;
                        LDSM_X2(b0, b1, bBase + off);
                        MMA_16816(d[0][fn], a[0][0], a[0][1], a[0][2], a[0][3], b0, b1);
                        MMA_16816(d[1][fn], a[1][0], a[1][1], a[1][2], a[1][3], b0, b1);
                    }
                }
            }
            if (elect_one_pred()) MBARRIER_ARRIVE(sb + SMEM_BAR + s * 16 + 8);
            if (++s == STAGES) { s = 0; ph ^= 1; }
        }
    }

    // ---- epilogue: D frag rows = out channel c, cols = w (2 consecutive) ----
    const int r = lid >> 2, cq = (lid & 3) * 2;
    #pragma unroll
    for (int fm = 0; fm < 2; fm++) {
        const int c0 = mt * M_TILE + wm * 32 + fm * 16 + r;
        const int c1 = c0 + 8;
        const float bv0 = bias[c0], bv1 = bias[c1];
        const float* xr0 = xsl + (size_t)(nt * CDU_C + c0) * CDU_HW;
        const float* xr1 = xsl + (size_t)(nt * CDU_C + c1) * CDU_HW;
        float* or0 = osl + (size_t)(nt * CDU_C + c0) * CDU_HW;
        float* or1 = osl + (size_t)(nt * CDU_C + c1) * CDU_HW;
        #pragma unroll
        for (int fn = 0; fn < 6; fn++) {
            const int w0 = wn * 48 + fn * 8 + cq;
            float2 xv0 = *reinterpret_cast<const float2*>(xr0 + w0);
            float2 xv1 = *reinterpret_cast<const float2*>(xr1 + w0);
            float2 o0, o1;
            o0.x = fmaxf(d[fm][fn][0] + bv0, 0.f) + xv0.x;
            o0.y = fmaxf(d[fm][fn][1] + bv0, 0.f) + xv0.y;
            o1.x = fmaxf(d[fm][fn][2] + bv1, 0.f) + xv1.x;
            o1.y = fmaxf(d[fm][fn][3] + bv1, 0.f) + xv1.y;
            *reinterpret_cast<float2*>(or0 + w0) = o0;
            *reinterpret_cast<float2*>(or1 + w0) = o1;
            // carry (fp16, K-major [nw][c]) for the next step's B operand
            const size_t nwb = (size_t)(nt * N_TILE + w0);
            g_carry[nwb * CDU_C + c0]       = __float2half(o0.x);
            g_carry[(nwb + 1) * CDU_C + c0] = __float2half(o0.y);
            g_carry[nwb * CDU_C + c1]       = __float2half(o1.x);
            g_carry[(nwb + 1) * CDU_C + c1] = __float2half(o1.y);
        }
    }
}

// ---------------------------------------------------------------------------
// Host
// ---------------------------------------------------------------------------
typedef CUresult (*cdu_encode_fn)(CUtensorMap*, CUtensorMapDataType, cuuint32_t, void*,
                                  const cuuint64_t*, const cuuint64_t*, const cuuint32_t*,
                                  const cuuint32_t*, CUtensorMapInterleave, CUtensorMapSwizzle,
                                  CUtensorMapL2promotion, CUtensorMapFloatOOBfill);

extern "C" void kernel_launch(void* const* d_in, const int* in_sizes, int n_in,
                              void* d_out, int out_size) {
    const float* fea = (const float*)d_in[0];
    const float* Wt  = (const float*)d_in[1];
    const float* b   = (const float*)d_in[2];
    float* out = (float*)d_out;

    void* whp = nullptr;  cudaGetSymbolAddress(&whp, g_Wh);
    void* cp  = nullptr;  cudaGetSymbolAddress(&cp, g_carry);

    cdu_encode_fn enc = nullptr;
    cudaDriverEntryPointQueryResult qr;
    cudaGetDriverEntryPointByVersion("cuTensorMapEncodeTiled", (void**)&enc, 12000,
                                     cudaEnableDefault, &qr);

    CUtensorMap mapA, mapB;
    {
        cuuint64_t dimsA[2]  = {CDU_C, CDU_C};
        cuuint64_t stride[1] = {CDU_C * sizeof(__half)};
        cuuint32_t boxA[2]   = {KC, M_TILE};
        cuuint32_t es[2]     = {1, 1};
        enc(&mapA, CU_TENSOR_MAP_DATA_TYPE_FLOAT16, 2, whp, dimsA, stride, boxA, es,
            CU_TENSOR_MAP_INTERLEAVE_NONE, CU_TENSOR_MAP_SWIZZLE_128B,
            CU_TENSOR_MAP_L2_PROMOTION_L2_128B, CU_TENSOR_MAP_FLOAT_OOB_FILL_NONE);
        cuuint64_t dimsB[2]  = {CDU_C, CDU_NW};
        cuuint32_t boxB[2]   = {KC, N_TILE};
        enc(&mapB, CU_TENSOR_MAP_DATA_TYPE_FLOAT16, 2, cp, dimsB, stride, boxB, es,
            CU_TENSOR_MAP_INTERLEAVE_NONE, CU_TENSOR_MAP_SWIZZLE_128B,
            CU_TENSOR_MAP_L2_PROMOTION_L2_128B, CU_TENSOR_MAP_FLOAT_OOB_FILL_NONE);
    }

    cudaFuncSetAttribute(cdu_step_kernel, cudaFuncAttributeMaxDynamicSharedMemorySize, SMEM_TOTAL);

    cdu_prep_kernel<<<PREP_BLOCKS, PREP_THREADS>>>(Wt, fea, out);

    dim3 grid(CDU_C / M_TILE, CDU_NW / N_TILE);   // (32, 4)
    // forward scan: h = 1..47
    for (int h = 1; h < CDU_H; h++)
        cdu_step_kernel<<<grid, 160, SMEM_TOTAL>>>(mapA, mapB, fea + h * CDU_W, out + h * CDU_W, b);
    // backward scan: h = 46..0 (x = down[h] staged in out)
    for (int h = CDU_H - 2; h >= 0; h--)
        cdu_step_kernel<<<grid, 160, SMEM_TOTAL>>>(mapA, mapB, out + h * CDU_W, out + h * CDU_W, b);
}

// round 16
// speedup vs baseline: 2.1739x; 1.0136x over previous
#include <cuda_runtime.h>
#include <cuda.h>
#include <cuda_fp16.h>
#include <cstdint>

// ============================================================================
// convDU: bidirectional recurrent conv along H.
//   step: y = relu(Wm @ carry + b) + x     (Wm = W[:,:,4,0], 2048x2048)
// 94 serial GEMM steps of [2048x2048]x[2048x384].
// Base-ISA tensor cores: TMA+mbarrier pipeline -> ldmatrix -> mma.sync
// m16n8k16 f16, fp32 accum.
// R15 validated the sync-cost model: halving mbarrier waits/step (32->16)
// bought 1.18us/step. R16 doubles again: each stage carries FOUR K-chunks
// (K=256/stage, 8 TMA loads, one mbarrier, expect_tx=80KB), STAGES 3->2.
// Consumers wait/arrive 8x per step. Fragments/MMA/epilogue byte-identical
// to R5/R14/R15 (best: 1154.7us).
// ============================================================================

#define CDU_C   2048
#define CDU_NB  4
#define CDU_H   48
#define CDU_W   96
#define CDU_NW  (CDU_NB * CDU_W)     // 384
#define CDU_HW  (CDU_H * CDU_W)      // 4608

#define M_TILE  64
#define N_TILE  96                   // one image's w-columns per CTA
#define KC      64                   // k elems per TMA box (128B SW128 row)
#define CPS     4                    // K-chunks per pipeline stage (K=256/stage)
#define SITERS  (CDU_C / (KC * CPS)) // 8 stage-iterations
#define STAGES  2

#define A_CHUNK_BYTES (M_TILE * 128)             // 8192
#define B_CHUNK_BYTES (N_TILE * 128)             // 12288
#define A_STAGE_BYTES (CPS * A_CHUNK_BYTES)      // 32768
#define B_STAGE_BYTES (CPS * B_CHUNK_BYTES)      // 49152
#define SMEM_BAR      64                         // full[s] @ 64+16s, empty[s] @ +8
#define SMEM_A        1024
#define SMEM_B        (SMEM_A + STAGES * A_STAGE_BYTES)     // 66560
#define SMEM_TOTAL    (SMEM_B + STAGES * B_STAGE_BYTES)     // 164864

// fp16 scratch: converted weight matrix + recurrent carry (K-major [nw][c])
__device__ __align__(16) __half g_Wh[CDU_C * CDU_C];
__device__ __align__(16) __half g_carry[CDU_NW * CDU_C];

// ---------------------------------------------------------------------------
// PTX helpers (base-ISA only)
// ---------------------------------------------------------------------------
__device__ __forceinline__ uint32_t elect_one_pred() {
    uint32_t pred;
    asm volatile(
        "{\n\t.reg .pred p;\n\telect.sync _|p, 0xFFFFFFFF;\n\t"
        "selp.b32 %0, 1, 0, p;\n\t}" : "=r"(pred));
    return pred;
}
__device__ __forceinline__ uint32_t smem_to_u32(const void* p) {
    uint32_t a;
    asm("{ .reg .u64 t; cvta.to.shared.u64 t, %1; cvt.u32.u64 %0, t; }" : "=r"(a) : "l"(p));
    return a;
}

#define MBARRIER_INIT(addr, cnt) \
    asm volatile("mbarrier.init.shared.b64 [%0], %1;" :: "r"((uint32_t)(addr)), "r"((uint32_t)(cnt)) : "memory")
#define MBARRIER_EXPECT_TX(addr, bytes) \
    asm volatile("mbarrier.arrive.expect_tx.shared.b64 _, [%0], %1;" :: "r"((uint32_t)(addr)), "r"((uint32_t)(bytes)) : "memory")
#define MBARRIER_ARRIVE(addr) \
    asm volatile("mbarrier.arrive.shared.b64 _, [%0];" :: "r"((uint32_t)(addr)) : "memory")

#define MBARRIER_WAIT_PARITY(mbar_smem_addr, phase_parity) do { \
    uint32_t _mbar = (uint32_t)(mbar_smem_addr); \
    uint32_t _parity = (uint32_t)(phase_parity); \
    uint32_t _done; \
    asm volatile( \
        "{\n\t.reg .pred p;\n\t" \
        "mbarrier.try_wait.parity.acquire.cta.shared::cta.b64 p, [%1], %2;\n\t" \
        "selp.b32 %0, 1, 0, p;\n\t}" \
        : "=r"(_done) : "r"(_mbar), "r"(_parity) : "memory"); \
    if (!_done) { \
        asm volatile( \
            "{\n\t.reg .pred P1;\n\t" \
            "WAIT_LOOP_%=:\n\t" \
            "mbarrier.try_wait.parity.acquire.cta.shared::cta.b64 P1, [%0], %1, 0x989680;\n\t" \
            "@P1 bra.uni WAIT_DONE_%=;\n\t" \
            "bra.uni WAIT_LOOP_%=;\n\t" \
            "WAIT_DONE_%=:\n\t}" \
            :: "r"(_mbar), "r"(_parity) : "memory"); \
    } \
} while (0)

__device__ __forceinline__ void tma_load_2d(uint32_t smem_addr, const void* tmap,
                                            int32_t cx, int32_t cy, uint32_t mbar) {
    asm volatile(
        "cp.async.bulk.tensor.2d.shared::cta.global.tile.mbarrier::complete_tx::bytes "
        "[%0], [%1, {%2, %3}], [%4];"
        :: "r"(smem_addr), "l"(tmap), "r"(cx), "r"(cy), "r"(mbar) : "memory");
}

#define LDSM_X4(r0, r1, r2, r3, addr) \
    asm volatile("ldmatrix.sync.aligned.m8n8.x4.shared.b16 {%0,%1,%2,%3}, [%4];" \
        : "=r"(r0), "=r"(r1), "=r"(r2), "=r"(r3) : "r"(addr))
#define LDSM_X2(r0, r1, addr) \
    asm volatile("ldmatrix.sync.aligned.m8n8.x2.shared.b16 {%0,%1}, [%2];" \
        : "=r"(r0), "=r"(r1) : "r"(addr))

#define MMA_16816(d, a0, a1, a2, a3, b0, b1) \
    asm volatile("mma.sync.aligned.m16n8k16.row.col.f32.f16.f16.f32 " \
        "{%0,%1,%2,%3}, {%4,%5,%6,%7}, {%8,%9}, {%0,%1,%2,%3};" \
        : "+f"((d)[0]), "+f"((d)[1]), "+f"((d)[2]), "+f"((d)[3]) \
        : "r"(a0), "r"(a1), "r"(a2), "r"(a3), "r"(b0), "r"(b1))

// ---------------------------------------------------------------------------
// Merged prep kernel (R14): W conversion + h=0 init in ONE launch.
// ---------------------------------------------------------------------------
#define PREP_BLOCKS  1184            // 148 SMs x 8 blocks
#define PREP_THREADS 256

__global__ void __launch_bounds__(PREP_THREADS)
cdu_prep_kernel(const float* __restrict__ Wsrc,
                const float* __restrict__ fea,
                float* __restrict__ out) {
    const int gstride = PREP_BLOCKS * PREP_THREADS;
    int g = blockIdx.x * PREP_THREADS + threadIdx.x;
    // init0: carry/out for h = 0
    for (int i = g; i < CDU_C * CDU_NW; i += gstride) {
        int c = i / CDU_NW, nw = i % CDU_NW;
        int n = nw / CDU_W, w = nw % CDU_W;
        size_t gi = (size_t)(n * CDU_C + c) * CDU_HW + w;  // h = 0
        float v = fea[gi];
        out[gi] = v;
        g_carry[(size_t)nw * CDU_C + c] = __float2half(v);
    }
    // wconv: W[o, c, 4, 0] -> fp16
    for (int i = g; i < CDU_C * CDU_C; i += gstride)
        g_Wh[i] = __float2half(Wsrc[(size_t)i * 9 + 4]);
}

// ---------------------------------------------------------------------------
// One recurrence step: D = relu(Wm @ carry + b) + x ; out/carry <- D
// Grid (32 m-tiles, 4 n-tiles) = 128 CTAs; 160 threads:
//   warps 0-3: ldmatrix + mma.sync consumers (warp tile m32 x n48)
//   warp  4  : TMA producer (4 chunks = 8 TMA loads per stage)
// ---------------------------------------------------------------------------
__global__ void __launch_bounds__(160, 1)
cdu_step_kernel(const __grid_constant__ CUtensorMap mapA,
                const __grid_constant__ CUtensorMap mapB,
                const float* __restrict__ xsl,      // x slice base (already + h*W)
                float* __restrict__ osl,            // out slice base (already + h*W)
                const float* __restrict__ bias)
{
    extern __shared__ __align__(1024) char smem[];
    uint32_t sb = smem_to_u32(smem);
    const int tid = threadIdx.x, wid = tid >> 5, lid = tid & 31;
    const int mt = blockIdx.x, nt = blockIdx.y;

    if (tid == 0) {
        for (int s = 0; s < STAGES; s++) {
            MBARRIER_INIT(sb + SMEM_BAR + s * 16, 1);       // full: 1 tx-arrive
            MBARRIER_INIT(sb + SMEM_BAR + s * 16 + 8, 4);   // empty: 4 consumer warps
        }
    }
    __syncthreads();

    if (wid == 4) {
        // ---- TMA producer: one mbarrier per 4-chunk stage ----
        if (elect_one_pred()) {
            int s = 0, j = 0;
            for (int it = 0; it < SITERS; it++) {
                if (j > 0) MBARRIER_WAIT_PARITY(sb + SMEM_BAR + s * 16 + 8, (j - 1) & 1);
                MBARRIER_EXPECT_TX(sb + SMEM_BAR + s * 16, A_STAGE_BYTES + B_STAGE_BYTES);
                const int k0 = it * (KC * CPS);
                #pragma unroll
                for (int c = 0; c < CPS; c++) {
                    tma_load_2d(sb + SMEM_A + s * A_STAGE_BYTES + c * A_CHUNK_BYTES, &mapA,
                                k0 + c * KC, mt * M_TILE, sb + SMEM_BAR + s * 16);
                    tma_load_2d(sb + SMEM_B + s * B_STAGE_BYTES + c * B_CHUNK_BYTES, &mapB,
                                k0 + c * KC, nt * N_TILE, sb + SMEM_BAR + s * 16);
                }
                if (++s == STAGES) { s = 0; ++j; }
            }
        }
        return;
    }

    // ---- consumers: warps 0..3, warp tile m32 x n48 ----
    const int wm = wid & 1;        // m offset = wm*32
    const int wn = wid >> 1;       // n offset = wn*48

    float d[2][6][4];
    #pragma unroll
    for (int fm = 0; fm < 2; fm++)
        #pragma unroll
        for (int fn = 0; fn < 6; fn++)
            #pragma unroll
            for (int q = 0; q < 4; q++) d[fm][fn][q] = 0.f;

    {
        int s = 0, ph = 0;
        for (int it = 0; it < SITERS; it++) {
            MBARRIER_WAIT_PARITY(sb + SMEM_BAR + s * 16, ph);
            #pragma unroll
            for (int c = 0; c < CPS; c++) {
                const uint32_t aBase = sb + SMEM_A + s * A_STAGE_BYTES + c * A_CHUNK_BYTES;
                const uint32_t bBase = sb + SMEM_B + s * B_STAGE_BYTES + c * B_CHUNK_BYTES;
                #pragma unroll
                for (int kk = 0; kk < 4; kk++) {
                    uint32_t a[2][4];
                    #pragma unroll
                    for (int fm = 0; fm < 2; fm++) {
                        int row = wm * 32 + fm * 16 + (lid & 15);
                        int col = kk * 32 + ((lid >> 4) << 4);
                        uint32_t off = row * 128 + (col ^ ((row & 7) << 4));  // SW128
                        LDSM_X4(a[fm][0], a[fm][1], a[fm][2], a[fm][3], aBase + off);
                    }
                    #pragma unroll
                    for (int fn = 0; fn < 6; fn++) {
                        int row = wn * 48 + fn * 8 + (lid & 7);
                        int col = kk * 32 + (((lid >> 3) & 1) << 4);
                        uint32_t off = row * 128 + (col ^ ((row & 7) << 4));  // SW128
                        uint32_t b0, b1;
                        LDSM_X2(b0, b1, bBase + off);
                        MMA_16816(d[0][fn], a[0][0], a[0][1], a[0][2], a[0][3], b0, b1);
                        MMA_16816(d[1][fn], a[1][0], a[1][1], a[1][2], a[1][3], b0, b1);
                    }
                }
            }
            if (elect_one_pred()) MBARRIER_ARRIVE(sb + SMEM_BAR + s * 16 + 8);
            if (++s == STAGES) { s = 0; ph ^= 1; }
        }
    }

    // ---- epilogue: D frag rows = out channel c, cols = w (2 consecutive) ----
    const int r = lid >> 2, cq = (lid & 3) * 2;
    #pragma unroll
    for (int fm = 0; fm < 2; fm++) {
        const int c0 = mt * M_TILE + wm * 32 + fm * 16 + r;
        const int c1 = c0 + 8;
        const float bv0 = bias[c0], bv1 = bias[c1];
        const float* xr0 = xsl + (size_t)(nt * CDU_C + c0) * CDU_HW;
        const float* xr1 = xsl + (size_t)(nt * CDU_C + c1) * CDU_HW;
        float* or0 = osl + (size_t)(nt * CDU_C + c0) * CDU_HW;
        float* or1 = osl + (size_t)(nt * CDU_C + c1) * CDU_HW;
        #pragma unroll
        for (int fn = 0; fn < 6; fn++) {
            const int w0 = wn * 48 + fn * 8 + cq;
            float2 xv0 = *reinterpret_cast<const float2*>(xr0 + w0);
            float2 xv1 = *reinterpret_cast<const float2*>(xr1 + w0);
            float2 o0, o1;
            o0.x = fmaxf(d[fm][fn][0] + bv0, 0.f) + xv0.x;
            o0.y = fmaxf(d[fm][fn][1] + bv0, 0.f) + xv0.y;
            o1.x = fmaxf(d[fm][fn][2] + bv1, 0.f) + xv1.x;
            o1.y = fmaxf(d[fm][fn][3] + bv1, 0.f) + xv1.y;
            *reinterpret_cast<float2*>(or0 + w0) = o0;
            *reinterpret_cast<float2*>(or1 + w0) = o1;
            // carry (fp16, K-major [nw][c]) for the next step's B operand
            const size_t nwb = (size_t)(nt * N_TILE + w0);
            g_carry[nwb * CDU_C + c0]       = __float2half(o0.x);
            g_carry[(nwb + 1) * CDU_C + c0] = __float2half(o0.y);
            g_carry[nwb * CDU_C + c1]       = __float2half(o1.x);
            g_carry[(nwb + 1) * CDU_C + c1] = __float2half(o1.y);
        }
    }
}

// ---------------------------------------------------------------------------
// Host
// ---------------------------------------------------------------------------
typedef CUresult (*cdu_encode_fn)(CUtensorMap*, CUtensorMapDataType, cuuint32_t, void*,
                                  const cuuint64_t*, const cuuint64_t*, const cuuint32_t*,
                                  const cuuint32_t*, CUtensorMapInterleave, CUtensorMapSwizzle,
                                  CUtensorMapL2promotion, CUtensorMapFloatOOBfill);

extern "C" void kernel_launch(void* const* d_in, const int* in_sizes, int n_in,
                              void* d_out, int out_size) {
    const float* fea = (const float*)d_in[0];
    const float* Wt  = (const float*)d_in[1];
    const float* b   = (const float*)d_in[2];
    float* out = (float*)d_out;

    void* whp = nullptr;  cudaGetSymbolAddress(&whp, g_Wh);
    void* cp  = nullptr;  cudaGetSymbolAddress(&cp, g_carry);

    cdu_encode_fn enc = nullptr;
    cudaDriverEntryPointQueryResult qr;
    cudaGetDriverEntryPointByVersion("cuTensorMapEncodeTiled", (void**)&enc, 12000,
                                     cudaEnableDefault, &qr);

    CUtensorMap mapA, mapB;
    {
        cuuint64_t dimsA[2]  = {CDU_C, CDU_C};
        cuuint64_t stride[1] = {CDU_C * sizeof(__half)};
        cuuint32_t boxA[2]   = {KC, M_TILE};
        cuuint32_t es[2]     = {1, 1};
        enc(&mapA, CU_TENSOR_MAP_DATA_TYPE_FLOAT16, 2, whp, dimsA, stride, boxA, es,
            CU_TENSOR_MAP_INTERLEAVE_NONE, CU_TENSOR_MAP_SWIZZLE_128B,
            CU_TENSOR_MAP_L2_PROMOTION_L2_128B, CU_TENSOR_MAP_FLOAT_OOB_FILL_NONE);
        cuuint64_t dimsB[2]  = {CDU_C, CDU_NW};
        cuuint32_t boxB[2]   = {KC, N_TILE};
        enc(&mapB, CU_TENSOR_MAP_DATA_TYPE_FLOAT16, 2, cp, dimsB, stride, boxB, es,
            CU_TENSOR_MAP_INTERLEAVE_NONE, CU_TENSOR_MAP_SWIZZLE_128B,
            CU_TENSOR_MAP_L2_PROMOTION_L2_128B, CU_TENSOR_MAP_FLOAT_OOB_FILL_NONE);
    }

    cudaFuncSetAttribute(cdu_step_kernel, cudaFuncAttributeMaxDynamicSharedMemorySize, SMEM_TOTAL);

    cdu_prep_kernel<<<PREP_BLOCKS, PREP_THREADS>>>(Wt, fea, out);

    dim3 grid(CDU_C / M_TILE, CDU_NW / N_TILE);   // (32, 4)
    // forward scan: h = 1..47
    for (int h = 1; h < CDU_H; h++)
        cdu_step_kernel<<<grid, 160, SMEM_TOTAL>>>(mapA, mapB, fea + h * CDU_W, out + h * CDU_W, b);
    // backward scan: h = 46..0 (x = down[h] staged in out)
    for (int h = CDU_H - 2; h >= 0; h--)
        cdu_step_kernel<<<grid, 160, SMEM_TOTAL>>>(mapA, mapB, out + h * CDU_W, out + h * CDU_W, b);
}

// round 17
// speedup vs baseline: 2.1903x; 1.0075x over previous
#include <cuda_runtime.h>
#include <cuda.h>
#include <cuda_fp16.h>
#include <cstdint>

// ============================================================================
// convDU: bidirectional recurrent conv along H.
//   step: y = relu(Wm @ carry + b) + x     (Wm = W[:,:,4,0], 2048x2048)
// 94 serial GEMM steps of [2048x2048]x[2048x384].
// Base-ISA tensor cores: TMA+mbarrier pipeline -> ldmatrix -> mma.sync
// m16n8k16 f16, fp32 accum.
// R15/R16 validated the per-stage sync-cost model (32->16->8 waits/step:
// 1231->1155->1139us). Wall/step (12.12us) is now at the measured legacy-mma
// HMMA floor. R17 shaves the inter-step carry tail: the serial dependency
// chain runs through g_carry, previously written as 24 scattered 2B STGs per
// thread (~12MB/step of wasted 32B write sectors). Stage the carry tile in
// (dead) pipeline smem and write coalesced 16B stores instead. Mainloop
// byte-identical to R16 (best: 1139.1us).
// ============================================================================

#define CDU_C   2048
#define CDU_NB  4
#define CDU_H   48
#define CDU_W   96
#define CDU_NW  (CDU_NB * CDU_W)     // 384
#define CDU_HW  (CDU_H * CDU_W)      // 4608

#define M_TILE  64
#define N_TILE  96                   // one image's w-columns per CTA
#define KC      64                   // k elems per TMA box (128B SW128 row)
#define CPS     4                    // K-chunks per pipeline stage (K=256/stage)
#define SITERS  (CDU_C / (KC * CPS)) // 8 stage-iterations
#define STAGES  2

#define A_CHUNK_BYTES (M_TILE * 128)             // 8192
#define B_CHUNK_BYTES (N_TILE * 128)             // 12288
#define A_STAGE_BYTES (CPS * A_CHUNK_BYTES)      // 32768
#define B_STAGE_BYTES (CPS * B_CHUNK_BYTES)      // 49152
#define SMEM_BAR      64                         // full[s] @ 64+16s, empty[s] @ +8
#define SMEM_A        1024
#define SMEM_B        (SMEM_A + STAGES * A_STAGE_BYTES)     // 66560
#define SMEM_TOTAL    (SMEM_B + STAGES * B_STAGE_BYTES)     // 164864

// fp16 scratch: converted weight matrix + recurrent carry (K-major [nw][c])
__device__ __align__(16) __half g_Wh[CDU_C * CDU_C];
__device__ __align__(16) __half g_carry[CDU_NW * CDU_C];

// ---------------------------------------------------------------------------
// PTX helpers (base-ISA only)
// ---------------------------------------------------------------------------
__device__ __forceinline__ uint32_t elect_one_pred() {
    uint32_t pred;
    asm volatile(
        "{\n\t.reg .pred p;\n\telect.sync _|p, 0xFFFFFFFF;\n\t"
        "selp.b32 %0, 1, 0, p;\n\t}" : "=r"(pred));
    return pred;
}
__device__ __forceinline__ uint32_t smem_to_u32(const void* p) {
    uint32_t a;
    asm("{ .reg .u64 t; cvta.to.shared.u64 t, %1; cvt.u32.u64 %0, t; }" : "=r"(a) : "l"(p));
    return a;
}

#define MBARRIER_INIT(addr, cnt) \
    asm volatile("mbarrier.init.shared.b64 [%0], %1;" :: "r"((uint32_t)(addr)), "r"((uint32_t)(cnt)) : "memory")
#define MBARRIER_EXPECT_TX(addr, bytes) \
    asm volatile("mbarrier.arrive.expect_tx.shared.b64 _, [%0], %1;" :: "r"((uint32_t)(addr)), "r"((uint32_t)(bytes)) : "memory")
#define MBARRIER_ARRIVE(addr) \
    asm volatile("mbarrier.arrive.shared.b64 _, [%0];" :: "r"((uint32_t)(addr)) : "memory")

#define MBARRIER_WAIT_PARITY(mbar_smem_addr, phase_parity) do { \
    uint32_t _mbar = (uint32_t)(mbar_smem_addr); \
    uint32_t _parity = (uint32_t)(phase_parity); \
    uint32_t _done; \
    asm volatile( \
        "{\n\t.reg .pred p;\n\t" \
        "mbarrier.try_wait.parity.acquire.cta.shared::cta.b64 p, [%1], %2;\n\t" \
        "selp.b32 %0, 1, 0, p;\n\t}" \
        : "=r"(_done) : "r"(_mbar), "r"(_parity) : "memory"); \
    if (!_done) { \
        asm volatile( \
            "{\n\t.reg .pred P1;\n\t" \
            "WAIT_LOOP_%=:\n\t" \
            "mbarrier.try_wait.parity.acquire.cta.shared::cta.b64 P1, [%0], %1, 0x989680;\n\t" \
            "@P1 bra.uni WAIT_DONE_%=;\n\t" \
            "bra.uni WAIT_LOOP_%=;\n\t" \
            "WAIT_DONE_%=:\n\t}" \
            :: "r"(_mbar), "r"(_parity) : "memory"); \
    } \
} while (0)

__device__ __forceinline__ void tma_load_2d(uint32_t smem_addr, const void* tmap,
                                            int32_t cx, int32_t cy, uint32_t mbar) {
    asm volatile(
        "cp.async.bulk.tensor.2d.shared::cta.global.tile.mbarrier::complete_tx::bytes "
        "[%0], [%1, {%2, %3}], [%4];"
        :: "r"(smem_addr), "l"(tmap), "r"(cx), "r"(cy), "r"(mbar) : "memory");
}

#define LDSM_X4(r0, r1, r2, r3, addr) \
    asm volatile("ldmatrix.sync.aligned.m8n8.x4.shared.b16 {%0,%1,%2,%3}, [%4];" \
        : "=r"(r0), "=r"(r1), "=r"(r2), "=r"(r3) : "r"(addr))
#define LDSM_X2(r0, r1, addr) \
    asm volatile("ldmatrix.sync.aligned.m8n8.x2.shared.b16 {%0,%1}, [%2];" \
        : "=r"(r0), "=r"(r1) : "r"(addr))

#define MMA_16816(d, a0, a1, a2, a3, b0, b1) \
    asm volatile("mma.sync.aligned.m16n8k16.row.col.f32.f16.f16.f32 " \
        "{%0,%1,%2,%3}, {%4,%5,%6,%7}, {%8,%9}, {%0,%1,%2,%3};" \
        : "+f"((d)[0]), "+f"((d)[1]), "+f"((d)[2]), "+f"((d)[3]) \
        : "r"(a0), "r"(a1), "r"(a2), "r"(a3), "r"(b0), "r"(b1))

// ---------------------------------------------------------------------------
// Merged prep kernel (R14): W conversion + h=0 init in ONE launch.
// ---------------------------------------------------------------------------
#define PREP_BLOCKS  1184            // 148 SMs x 8 blocks
#define PREP_THREADS 256

__global__ void __launch_bounds__(PREP_THREADS)
cdu_prep_kernel(const float* __restrict__ Wsrc,
                const float* __restrict__ fea,
                float* __restrict__ out) {
    const int gstride = PREP_BLOCKS * PREP_THREADS;
    int g = blockIdx.x * PREP_THREADS + threadIdx.x;
    // init0: carry/out for h = 0
    for (int i = g; i < CDU_C * CDU_NW; i += gstride) {
        int c = i / CDU_NW, nw = i % CDU_NW;
        int n = nw / CDU_W, w = nw % CDU_W;
        size_t gi = (size_t)(n * CDU_C + c) * CDU_HW + w;  // h = 0
        float v = fea[gi];
        out[gi] = v;
        g_carry[(size_t)nw * CDU_C + c] = __float2half(v);
    }
    // wconv: W[o, c, 4, 0] -> fp16
    for (int i = g; i < CDU_C * CDU_C; i += gstride)
        g_Wh[i] = __float2half(Wsrc[(size_t)i * 9 + 4]);
}

// ---------------------------------------------------------------------------
// One recurrence step: D = relu(Wm @ carry + b) + x ; out/carry <- D
// Grid (32 m-tiles, 4 n-tiles) = 128 CTAs; 160 threads:
//   warps 0-3: ldmatrix + mma.sync consumers (warp tile m32 x n48)
//   warp  4  : TMA producer (4 chunks = 8 TMA loads per stage)
// ---------------------------------------------------------------------------
__global__ void __launch_bounds__(160, 1)
cdu_step_kernel(const __grid_constant__ CUtensorMap mapA,
                const __grid_constant__ CUtensorMap mapB,
                const float* __restrict__ xsl,      // x slice base (already + h*W)
                float* __restrict__ osl,            // out slice base (already + h*W)
                const float* __restrict__ bias)
{
    extern __shared__ __align__(1024) char smem[];
    uint32_t sb = smem_to_u32(smem);
    const int tid = threadIdx.x, wid = tid >> 5, lid = tid & 31;
    const int mt = blockIdx.x, nt = blockIdx.y;

    if (tid == 0) {
        for (int s = 0; s < STAGES; s++) {
            MBARRIER_INIT(sb + SMEM_BAR + s * 16, 1);       // full: 1 tx-arrive
            MBARRIER_INIT(sb + SMEM_BAR + s * 16 + 8, 4);   // empty: 4 consumer warps
        }
    }
    __syncthreads();

    if (wid == 4) {
        // ---- TMA producer: one mbarrier per 4-chunk stage ----
        if (elect_one_pred()) {
            int s = 0, j = 0;
            for (int it = 0; it < SITERS; it++) {
                if (j > 0) MBARRIER_WAIT_PARITY(sb + SMEM_BAR + s * 16 + 8, (j - 1) & 1);
                MBARRIER_EXPECT_TX(sb + SMEM_BAR + s * 16, A_STAGE_BYTES + B_STAGE_BYTES);
                const int k0 = it * (KC * CPS);
                #pragma unroll
                for (int c = 0; c < CPS; c++) {
                    tma_load_2d(sb + SMEM_A + s * A_STAGE_BYTES + c * A_CHUNK_BYTES, &mapA,
                                k0 + c * KC, mt * M_TILE, sb + SMEM_BAR + s * 16);
                    tma_load_2d(sb + SMEM_B + s * B_STAGE_BYTES + c * B_CHUNK_BYTES, &mapB,
                                k0 + c * KC, nt * N_TILE, sb + SMEM_BAR + s * 16);
                }
                if (++s == STAGES) { s = 0; ++j; }
            }
        }
        return;
    }

    // ---- consumers: warps 0..3, warp tile m32 x n48 ----
    const int wm = wid & 1;        // m offset = wm*32
    const int wn = wid >> 1;       // n offset = wn*48

    float d[2][6][4];
    #pragma unroll
    for (int fm = 0; fm < 2; fm++)
        #pragma unroll
        for (int fn = 0; fn < 6; fn++)
            #pragma unroll
            for (int q = 0; q < 4; q++) d[fm][fn][q] = 0.f;

    {
        int s = 0, ph = 0;
        for (int it = 0; it < SITERS; it++) {
            MBARRIER_WAIT_PARITY(sb + SMEM_BAR + s * 16, ph);
            #pragma unroll
            for (int c = 0; c < CPS; c++) {
                const uint32_t aBase = sb + SMEM_A + s * A_STAGE_BYTES + c * A_CHUNK_BYTES;
                const uint32_t bBase = sb + SMEM_B + s * B_STAGE_BYTES + c * B_CHUNK_BYTES;
                #pragma unroll
                for (int kk = 0; kk < 4; kk++) {
                    uint32_t a[2][4];
                    #pragma unroll
                    for (int fm = 0; fm < 2; fm++) {
                        int row = wm * 32 + fm * 16 + (lid & 15);
                        int col = kk * 32 + ((lid >> 4) << 4);
                        uint32_t off = row * 128 + (col ^ ((row & 7) << 4));  // SW128
                        LDSM_X4(a[fm][0], a[fm][1], a[fm][2], a[fm][3], aBase + off);
                    }
                    #pragma unroll
                    for (int fn = 0; fn < 6; fn++) {
                        int row = wn * 48 + fn * 8 + (lid & 7);
                        int col = kk * 32 + (((lid >> 3) & 1) << 4);
                        uint32_t off = row * 128 + (col ^ ((row & 7) << 4));  // SW128
                        uint32_t b0, b1;
                        LDSM_X2(b0, b1, bBase + off);
                        MMA_16816(d[0][fn], a[0][0], a[0][1], a[0][2], a[0][3], b0, b1);
                        MMA_16816(d[1][fn], a[1][0], a[1][1], a[1][2], a[1][3], b0, b1);
                    }
                }
            }
            if (elect_one_pred()) MBARRIER_ARRIVE(sb + SMEM_BAR + s * 16 + 8);
            if (++s == STAGES) { s = 0; ph ^= 1; }
        }
    }

    // ---- epilogue ----
    // All consumer warps done with the pipeline; all TMA data landed (final
    // full-wait) -> safe to reuse the stage-A smem region as a [96][64] fp16
    // carry-transpose staging buffer (12288B < A_STAGE_BYTES).
    asm volatile("bar.sync 2, 128;" ::: "memory");

    __half* st = reinterpret_cast<__half*>(smem + SMEM_A);
    const int r = lid >> 2, cq = (lid & 3) * 2;
    #pragma unroll
    for (int fm = 0; fm < 2; fm++) {
        const int cl0 = wm * 32 + fm * 16 + r;         // local channel 0..63
        const int cl1 = cl0 + 8;
        const int c0 = mt * M_TILE + cl0;
        const int c1 = mt * M_TILE + cl1;
        const float bv0 = bias[c0], bv1 = bias[c1];
        const float* xr0 = xsl + (size_t)(nt * CDU_C + c0) * CDU_HW;
        const float* xr1 = xsl + (size_t)(nt * CDU_C + c1) * CDU_HW;
        float* or0 = osl + (size_t)(nt * CDU_C + c0) * CDU_HW;
        float* or1 = osl + (size_t)(nt * CDU_C + c1) * CDU_HW;
        #pragma unroll
        for (int fn = 0; fn < 6; fn++) {
            const int w0 = wn * 48 + fn * 8 + cq;
            float2 xv0 = *reinterpret_cast<const float2*>(xr0 + w0);
            float2 xv1 = *reinterpret_cast<const float2*>(xr1 + w0);
            float2 o0, o1;
            o0.x = fmaxf(d[fm][fn][0] + bv0, 0.f) + xv0.x;
            o0.y = fmaxf(d[fm][fn][1] + bv0, 0.f) + xv0.y;
            o1.x = fmaxf(d[fm][fn][2] + bv1, 0.f) + xv1.x;
            o1.y = fmaxf(d[fm][fn][3] + bv1, 0.f) + xv1.y;
            *reinterpret_cast<float2*>(or0 + w0) = o0;
            *reinterpret_cast<float2*>(or1 + w0) = o1;
            st[(w0 + 0) * M_TILE + cl0] = __float2half(o0.x);
            st[(w0 + 1) * M_TILE + cl0] = __float2half(o0.y);
            st[(w0 + 0) * M_TILE + cl1] = __float2half(o1.x);
            st[(w0 + 1) * M_TILE + cl1] = __float2half(o1.y);
        }
    }

    asm volatile("bar.sync 2, 128;" ::: "memory");

    // coalesced carry writeback: 96 rows x 128B, 8 x uint4 per row
    for (int i = tid; i < N_TILE * 8; i += 128) {
        const int row = i >> 3, seg = i & 7;
        uint4 v = *reinterpret_cast<const uint4*>(smem + SMEM_A + row * (M_TILE * 2) + seg * 16);
        *reinterpret_cast<uint4*>(&g_carry[(size_t)(nt * N_TILE + row) * CDU_C + mt * M_TILE + seg * 8]) = v;
    }
}

// ---------------------------------------------------------------------------
// Host
// ---------------------------------------------------------------------------
typedef CUresult (*cdu_encode_fn)(CUtensorMap*, CUtensorMapDataType, cuuint32_t, void*,
                                  const cuuint64_t*, const cuuint64_t*, const cuuint32_t*,
                                  const cuuint32_t*, CUtensorMapInterleave, CUtensorMapSwizzle,
                                  CUtensorMapL2promotion, CUtensorMapFloatOOBfill);

extern "C" void kernel_launch(void* const* d_in, const int* in_sizes, int n_in,
                              void* d_out, int out_size) {
    const float* fea = (const float*)d_in[0];
    const float* Wt  = (const float*)d_in[1];
    const float* b   = (const float*)d_in[2];
    float* out = (float*)d_out;

    void* whp = nullptr;  cudaGetSymbolAddress(&whp, g_Wh);
    void* cp  = nullptr;  cudaGetSymbolAddress(&cp, g_carry);

    cdu_encode_fn enc = nullptr;
    cudaDriverEntryPointQueryResult qr;
    cudaGetDriverEntryPointByVersion("cuTensorMapEncodeTiled", (void**)&enc, 12000,
                                     cudaEnableDefault, &qr);

    CUtensorMap mapA, mapB;
    {
        cuuint64_t dimsA[2]  = {CDU_C, CDU_C};
        cuuint64_t stride[1] = {CDU_C * sizeof(__half)};
        cuuint32_t boxA[2]   = {KC, M_TILE};
        cuuint32_t es[2]     = {1, 1};
        enc(&mapA, CU_TENSOR_MAP_DATA_TYPE_FLOAT16, 2, whp, dimsA, stride, boxA, es,
            CU_TENSOR_MAP_INTERLEAVE_NONE, CU_TENSOR_MAP_SWIZZLE_128B,
            CU_TENSOR_MAP_L2_PROMOTION_L2_128B, CU_TENSOR_MAP_FLOAT_OOB_FILL_NONE);
        cuuint64_t dimsB[2]  = {CDU_C, CDU_NW};
        cuuint32_t boxB[2]   = {KC, N_TILE};
        enc(&mapB, CU_TENSOR_MAP_DATA_TYPE_FLOAT16, 2, cp, dimsB, stride, boxB, es,
            CU_TENSOR_MAP_INTERLEAVE_NONE, CU_TENSOR_MAP_SWIZZLE_128B,
            CU_TENSOR_MAP_L2_PROMOTION_L2_128B, CU_TENSOR_MAP_FLOAT_OOB_FILL_NONE);
    }

    cudaFuncSetAttribute(cdu_step_kernel, cudaFuncAttributeMaxDynamicSharedMemorySize, SMEM_TOTAL);

    cdu_prep_kernel<<<PREP_BLOCKS, PREP_THREADS>>>(Wt, fea, out);

    dim3 grid(CDU_C / M_TILE, CDU_NW / N_TILE);   // (32, 4)
    // forward scan: h = 1..47
    for (int h = 1; h < CDU_H; h++)
        cdu_step_kernel<<<grid, 160, SMEM_TOTAL>>>(mapA, mapB, fea + h * CDU_W, out + h * CDU_W, b);
    // backward scan: h = 46..0 (x = down[h] staged in out)
    for (int h = CDU_H - 2; h >= 0; h--)
        cdu_step_kernel<<<grid, 160, SMEM_TOTAL>>>(mapA, mapB, out + h * CDU_W, out + h * CDU_W, b);
}